// round 9
// baseline (speedup 1.0000x reference)
#include <cuda_runtime.h>

// Tree shape: DEPTH=4, V=4.  n4=1, n3=5, n2=25, n1=125, n0=125.
#define NV   4
#define N1   125
#define N2   25
#define N3   5
#define NTHREADS 64   // 2 batch elements per thread -> 128 elems/block

typedef unsigned long long ull;

__device__ __forceinline__ float ex2f(float a) {
    float r;
    asm("ex2.approx.f32 %0, %1;" : "=f"(r) : "f"(a));
    return r;
}
__device__ __forceinline__ float lg2f(float a) {
    float r;
    asm("lg2.approx.f32 %0, %1;" : "=f"(r) : "f"(a));
    return r;
}

// ---- packed fp32x2 ops (Blackwell packed pipe; 2 FMAs per issue slot) ----
__device__ __forceinline__ ull fma2(ull a, ull b, ull c) {
    ull r;
    asm("fma.rn.f32x2 %0, %1, %2, %3;" : "=l"(r) : "l"(a), "l"(b), "l"(c));
    return r;
}
__device__ __forceinline__ ull mul2(ull a, ull b) {
    ull r;
    asm("mul.rn.f32x2 %0, %1, %2;" : "=l"(r) : "l"(a), "l"(b));
    return r;
}
__device__ __forceinline__ ull pack2(float x, float y) {
    ull r;
    asm("mov.b64 %0, {%1, %2};" : "=l"(r) : "f"(x), "f"(y));
    return r;
}
__device__ __forceinline__ void unpack2(ull a, float& x, float& y) {
    asm("mov.b64 {%0, %1}, %2;" : "=f"(x), "=f"(y) : "l"(a));
}

// Taylor coefficients of 2^s (s small): c_k = ln2^k / k!
#define TC5 0x3AAEC5193AAEC519ULL  // 1.3333558e-3
#define TC4 0x3C1D955B3C1D955BULL  // 9.6181291e-3
#define TC3 0x3D6357CF3D6357CFULL  // 5.5504109e-2
#define TC2 0x3E75FDF03E75FDF0ULL  // 2.4022651e-1
#define TC1 0x3F3172183F317218ULL  // 6.9314718e-1
#define TC0 0x3F8000003F800000ULL  // 1.0

// Packed 2^{4s} via degree-5 Taylor of 2^s then two squarings.
// |s| <= ~1 is safe (|t|=|4s| <= 4); rel err <= ~1e-4 worst case.
__device__ __forceinline__ ull exp2_4s(ull s) {
    ull p = fma2(TC5, s, TC4);
    p = fma2(p, s, TC3);
    p = fma2(p, s, TC2);
    p = fma2(p, s, TC1);
    p = fma2(p, s, TC0);   // p ~= 2^s
    p = mul2(p, p);        // 2^{2s}
    return mul2(p, p);     // 2^{4s}
}

// Level-1 node m, two batch elements (A,B) per thread.
//  sLam[m]  = (lam_m0, lam_m1, lam_m2, lam_m3)
//  sPw01[m] = { dup(pow_m0), dup(pow_m1) }           (plain, feeds MUFU)
//  sPw23[m] = { dup(0.25*pow_m2), dup(0.25*pow_m3) } (pre-scaled, feeds poly)
//  sC[m]    = lam0 const of the matching depth-0 node
// Vars 0,1 via MUFU ex2 (4 EX2); vars 2,3 via packed f32x2 poly (16 f32x2).
__device__ __forceinline__ void eval_f1(
    int m,
    const float4*     __restrict__ sLam,
    const ulonglong2* __restrict__ sPw01,
    const ulonglong2* __restrict__ sPw23,
    const float*      __restrict__ sC,
    ull lx0p, ull lx1p, ull lx2p, ull lx3p,
    float& fA, float& fB)
{
    const float4     L  = sLam[m];
    const ulonglong2 pa = sPw01[m];
    const ulonglong2 pb = sPw23[m];
    const float      c  = sC[m];

    // MUFU path (vars 0,1): args computed packed, consumed scalar (unpack free)
    const ull t0 = mul2(pa.x, lx0p);
    const ull t1 = mul2(pa.y, lx1p);
    float a0, b0, a1, b1;
    unpack2(t0, a0, b0);
    unpack2(t1, a1, b1);
    const float eA0 = ex2f(a0);
    const float eB0 = ex2f(b0);
    const float eA1 = ex2f(a1);
    const float eB1 = ex2f(b1);

    // Poly path (vars 2,3): fully packed, no ALU/MOV tail
    const ull v2 = exp2_4s(mul2(pb.x, lx2p));
    const ull v3 = exp2_4s(mul2(pb.y, lx3p));
    float v2A, v2B, v3A, v3B;
    unpack2(v2, v2A, v2B);
    unpack2(v3, v3A, v3B);

    fA = fmaf(L.x, eA0, fmaf(L.y, eA1, fmaf(L.z, v2A, fmaf(L.w, v3A, c))));
    fB = fmaf(L.x, eB0, fmaf(L.y, eB1, fmaf(L.z, v2B, fmaf(L.w, v3B, c))));
}

__global__
void nested_formula_kernel(const float4* __restrict__ x,      // (B, 4) as float4
                           const float*  __restrict__ lam0,   // (125,)
                           const float*  __restrict__ lam1,   // (125,4)
                           const float*  __restrict__ pow1,
                           const float*  __restrict__ lam2,   // (25,4)
                           const float*  __restrict__ pow2,
                           const float*  __restrict__ lam3,   // (5,4)
                           const float*  __restrict__ pow3,
                           const float*  __restrict__ lam4,   // (1,4)
                           const float*  __restrict__ pow4,
                           float* __restrict__ out,           // (B,)
                           int B) {
    __shared__ __align__(16) float4     sLam[N1];     // 2000 B
    __shared__ __align__(16) ulonglong2 sPw01[N1];    // 2000 B
    __shared__ __align__(16) ulonglong2 sPw23[N1];    // 2000 B
    __shared__               float      sC[N1];       //  500 B
    __shared__ __align__(16) float2     s2[N2 * NV];  //  800 B
    __shared__ __align__(16) float2     s3[N3 * NV];  //  160 B
    __shared__ __align__(16) float2     s4[NV];       //   32 B

    const int tid = threadIdx.x;
    for (int m = tid; m < N1; m += NTHREADS) {
        sLam[m] = make_float4(lam1[4*m+0], lam1[4*m+1], lam1[4*m+2], lam1[4*m+3]);
        ulonglong2 p01, p23;
        p01.x = pack2(pow1[4*m+0], pow1[4*m+0]);
        p01.y = pack2(pow1[4*m+1], pow1[4*m+1]);
        const float q2 = 0.25f * pow1[4*m+2];
        const float q3 = 0.25f * pow1[4*m+3];
        p23.x = pack2(q2, q2);
        p23.y = pack2(q3, q3);
        sPw01[m] = p01;
        sPw23[m] = p23;
        sC[m] = lam0[m];
    }
    for (int i = tid; i < N2 * NV; i += NTHREADS)
        s2[i] = make_float2(lam2[i], pow2[i]);
    if (tid < N3 * NV) s3[tid] = make_float2(lam3[tid], pow3[tid]);
    if (tid < NV)      s4[tid] = make_float2(lam4[tid], pow4[tid]);
    __syncthreads();

    const float4* v2p = (const float4*)s2;

    // Two batch elements per thread, coalesced within the block.
    const int b0 = blockIdx.x * (2 * NTHREADS) + tid;
    const int b1 = b0 + NTHREADS;

    const float4 xA = x[b0];
    const float4 xB = x[b1];
    const float lxA[4] = {lg2f(xA.x), lg2f(xA.y), lg2f(xA.z), lg2f(xA.w)};
    const float lxB[4] = {lg2f(xB.x), lg2f(xB.y), lg2f(xB.z), lg2f(xB.w)};
    const ull lx0p = pack2(lxA[0], lxB[0]);
    const ull lx1p = pack2(lxA[1], lxB[1]);
    const ull lx2p = pack2(lxA[2], lxB[2]);
    const ull lx3p = pack2(lxA[3], lxB[3]);

    float acc4A = 0.0f, acc4B = 0.0f;
    #pragma unroll 1
    for (int j = 0; j < 5; ++j) {          // 5 level-3 nodes (root's children)
        float acc3A = 0.0f, acc3B = 0.0f;
        #pragma unroll
        for (int kk = 0; kk < 5; ++kk) {   // 5 level-2 children of node j (unrolled)
            const int k = j * 5 + kk;
            float acc2A, acc2B;
            eval_f1(k * 5 + 4, sLam, sPw01, sPw23, sC,
                    lx0p, lx1p, lx2p, lx3p, acc2A, acc2B);
            const float4 p0 = v2p[2 * k];       // (lam_k0,pow_k0,lam_k1,pow_k1)
            const float4 p1 = v2p[2 * k + 1];   // (lam_k2,pow_k2,lam_k3,pow_k3)
            #pragma unroll
            for (int mm = 0; mm < 4; ++mm) {
                float fA, fB;
                eval_f1(k * 5 + mm, sLam, sPw01, sPw23, sC,
                        lx0p, lx1p, lx2p, lx3p, fA, fB);
                const float lam = (mm == 0) ? p0.x : (mm == 1) ? p0.z : (mm == 2) ? p1.x : p1.z;
                const float pw  = (mm == 0) ? p0.y : (mm == 1) ? p0.w : (mm == 2) ? p1.y : p1.w;
                acc2A = fmaf(lam * ex2f(pw * lxA[mm]), fA, acc2A);
                acc2B = fmaf(lam * ex2f(pw * lxB[mm]), fB, acc2B);
            }
            if (kk < 4) {
                const float2 lp = s3[j * 4 + kk];
                acc3A = fmaf(lp.x * ex2f(lp.y * lxA[kk]), acc2A, acc3A);
                acc3B = fmaf(lp.x * ex2f(lp.y * lxB[kk]), acc2B, acc3B);
            } else {
                acc3A += acc2A;
                acc3B += acc2B;
            }
        }
        if (j < 4) {
            const float lxjA = (j == 0) ? lxA[0] : (j == 1) ? lxA[1] : (j == 2) ? lxA[2] : lxA[3];
            const float lxjB = (j == 0) ? lxB[0] : (j == 1) ? lxB[1] : (j == 2) ? lxB[2] : lxB[3];
            const float2 lp = s4[j];
            acc4A = fmaf(lp.x * ex2f(lp.y * lxjA), acc3A, acc4A);
            acc4B = fmaf(lp.x * ex2f(lp.y * lxjB), acc3B, acc4B);
        } else {
            acc4A += acc3A;
            acc4B += acc3B;
        }
    }

    out[b0] = acc4A;
    out[b1] = acc4B;
}

extern "C" void kernel_launch(void* const* d_in, const int* in_sizes, int n_in,
                              void* d_out, int out_size) {
    // metadata order: x, lam0, lam1, pow1, lam2, pow2, lam3, pow3, lam4, pow4
    const float4* x    = (const float4*)d_in[0];
    const float*  lam0 = (const float*)d_in[1];
    const float*  lam1 = (const float*)d_in[2];
    const float*  pow1 = (const float*)d_in[3];
    const float*  lam2 = (const float*)d_in[4];
    const float*  pow2 = (const float*)d_in[5];
    const float*  lam3 = (const float*)d_in[6];
    const float*  pow3 = (const float*)d_in[7];
    const float*  lam4 = (const float*)d_in[8];
    const float*  pow4 = (const float*)d_in[9];
    float* out = (float*)d_out;

    const int B = in_sizes[0] / 4;                 // x has B*4 elements
    const int elemsPerBlock = 2 * NTHREADS;        // 128
    const int grid = (B + elemsPerBlock - 1) / elemsPerBlock;
    nested_formula_kernel<<<grid, NTHREADS>>>(x, lam0, lam1, pow1, lam2, pow2,
                                              lam3, pow3, lam4, pow4, out, B);
}